// round 1
// baseline (speedup 1.0000x reference)
#include <cuda_runtime.h>
#include <math.h>
#include <stdint.h>

// ---------------- problem constants ----------------
#define N_PTS   29696
#define N_IN_C  1024
#define E1_C    512
#define E2_C    512
#define E3_C    2048
#define NZ_C    32
#define D1_C    2048
#define D2_C    512
#define D3_C    512
#define K_C     100
#define EPS_C   1e-5f

// GEMM tiling
#define BM 128
#define BN 64
#define BK 16
// M blocks
#define MBLK (N_PTS / BM)          // 232
#define MSE_PARTIALS (MBLK * (N_IN_C / BN))  // 232*16 = 3712

// ---------------- scratch (static device globals; no allocation) ----------------
__device__ float g_bufA[(size_t)N_PTS * 2048];
__device__ float g_bufB[(size_t)N_PTS * 2048];
__device__ float g_zbuf[(size_t)N_PTS * NZ_C];
__device__ float g_q[(size_t)N_PTS * K_C];
__device__ int   g_pred[N_PTS];
__device__ float g_Scon[N_PTS];
__device__ float g_u[K_C];
__device__ float g_f[K_C];
__device__ int   g_cnt[K_C];
__device__ float g_S;
__device__ float g_uloss;
__device__ float g_msep[MSE_PARTIALS];
__device__ float g_klp[MBLK];

// ---------------- init ----------------
__global__ void init_kernel() {
    int t = threadIdx.x;
    if (t < K_C) g_cnt[t] = 0;
}

// ---------------- generic fp32 GEMM: C = [relu](A[MxK] @ W[KxN] + bias) ----------------
// 256 threads, 128x64 tile, 8x4 microtile. Requires M%128==0, K%16==0. N guarded.
__global__ __launch_bounds__(256) void gemm_relu(
    const float* __restrict__ A, const float* __restrict__ W,
    const float* __restrict__ bias, float* __restrict__ C,
    int M, int K, int N, int doRelu)
{
    __shared__ float As[BK][BM];
    __shared__ float Ws[BK][BN];
    const int tid = threadIdx.x;
    const int rowBlock = blockIdx.y * BM;
    const int colBlock = blockIdx.x * BN;
    const int tx = tid & 15;
    const int ty = tid >> 4;
    const int rBase = ty * 8;
    const int cBase = tx * 4;

    float acc[8][4];
#pragma unroll
    for (int i = 0; i < 8; i++)
#pragma unroll
        for (int j = 0; j < 4; j++) acc[i][j] = 0.f;

    const int aRow0 = tid >> 2;       // 0..63
    const int aF4   = tid & 3;        // 0..3
    const int wK    = tid >> 4;       // 0..15
    const int wC    = (tid & 15) * 4; // 0..60

    for (int k0 = 0; k0 < K; k0 += BK) {
        // load A tile (transposed into smem)
#pragma unroll
        for (int h = 0; h < 2; h++) {
            int r = aRow0 + h * 64;
            float4 v = *reinterpret_cast<const float4*>(
                &A[(size_t)(rowBlock + r) * K + k0 + aF4 * 4]);
            As[aF4 * 4 + 0][r] = v.x;
            As[aF4 * 4 + 1][r] = v.y;
            As[aF4 * 4 + 2][r] = v.z;
            As[aF4 * 4 + 3][r] = v.w;
        }
        // load W tile (guard N)
        {
            int col = colBlock + wC;
            float4 v = make_float4(0.f, 0.f, 0.f, 0.f);
            if (col + 3 < N) {
                v = *reinterpret_cast<const float4*>(&W[(size_t)(k0 + wK) * N + col]);
            } else {
                float tmp[4] = {0.f, 0.f, 0.f, 0.f};
                for (int j = 0; j < 4; j++)
                    if (col + j < N) tmp[j] = W[(size_t)(k0 + wK) * N + col + j];
                v = make_float4(tmp[0], tmp[1], tmp[2], tmp[3]);
            }
            *reinterpret_cast<float4*>(&Ws[wK][wC]) = v;
        }
        __syncthreads();
#pragma unroll
        for (int kk = 0; kk < BK; kk++) {
            float a[8], b[4];
#pragma unroll
            for (int i = 0; i < 8; i++) a[i] = As[kk][rBase + i];
#pragma unroll
            for (int j = 0; j < 4; j++) b[j] = Ws[kk][cBase + j];
#pragma unroll
            for (int i = 0; i < 8; i++)
#pragma unroll
                for (int j = 0; j < 4; j++) acc[i][j] = fmaf(a[i], b[j], acc[i][j]);
        }
        __syncthreads();
    }
#pragma unroll
    for (int i = 0; i < 8; i++) {
        int row = rowBlock + rBase + i;
#pragma unroll
        for (int j = 0; j < 4; j++) {
            int col = colBlock + cBase + j;
            if (col < N) {
                float v = acc[i][j] + bias[col];
                if (doRelu) v = fmaxf(v, 0.f);
                C[(size_t)row * N + col] = v;
            }
        }
    }
}

// ---------------- last GEMM fused with MSE vs x (no store of x_bar) ----------------
__global__ __launch_bounds__(256) void gemm_mse(
    const float* __restrict__ A, const float* __restrict__ W,
    const float* __restrict__ bias, const float* __restrict__ Xref,
    float* __restrict__ partial, int M, int K, int N)
{
    __shared__ float As[BK][BM];
    __shared__ float Ws[BK][BN];
    __shared__ float red[256];
    const int tid = threadIdx.x;
    const int rowBlock = blockIdx.y * BM;
    const int colBlock = blockIdx.x * BN;
    const int tx = tid & 15;
    const int ty = tid >> 4;
    const int rBase = ty * 8;
    const int cBase = tx * 4;

    float acc[8][4];
#pragma unroll
    for (int i = 0; i < 8; i++)
#pragma unroll
        for (int j = 0; j < 4; j++) acc[i][j] = 0.f;

    const int aRow0 = tid >> 2;
    const int aF4   = tid & 3;
    const int wK    = tid >> 4;
    const int wC    = (tid & 15) * 4;

    for (int k0 = 0; k0 < K; k0 += BK) {
#pragma unroll
        for (int h = 0; h < 2; h++) {
            int r = aRow0 + h * 64;
            float4 v = *reinterpret_cast<const float4*>(
                &A[(size_t)(rowBlock + r) * K + k0 + aF4 * 4]);
            As[aF4 * 4 + 0][r] = v.x;
            As[aF4 * 4 + 1][r] = v.y;
            As[aF4 * 4 + 2][r] = v.z;
            As[aF4 * 4 + 3][r] = v.w;
        }
        {
            int col = colBlock + wC;
            float4 v = *reinterpret_cast<const float4*>(&W[(size_t)(k0 + wK) * N + col]);
            *reinterpret_cast<float4*>(&Ws[wK][wC]) = v;
        }
        __syncthreads();
#pragma unroll
        for (int kk = 0; kk < BK; kk++) {
            float a[8], b[4];
#pragma unroll
            for (int i = 0; i < 8; i++) a[i] = As[kk][rBase + i];
#pragma unroll
            for (int j = 0; j < 4; j++) b[j] = Ws[kk][cBase + j];
#pragma unroll
            for (int i = 0; i < 8; i++)
#pragma unroll
                for (int j = 0; j < 4; j++) acc[i][j] = fmaf(a[i], b[j], acc[i][j]);
        }
        __syncthreads();
    }
    float mse = 0.f;
#pragma unroll
    for (int i = 0; i < 8; i++) {
        int row = rowBlock + rBase + i;
#pragma unroll
        for (int j = 0; j < 4; j++) {
            int col = colBlock + cBase + j;
            float v = acc[i][j] + bias[col];
            float d = v - Xref[(size_t)row * N + col];
            mse += d * d;
        }
    }
    red[tid] = mse;
    __syncthreads();
    for (int o = 128; o > 0; o >>= 1) {
        if (tid < o) red[tid] += red[tid + o];
        __syncthreads();
    }
    if (tid == 0) partial[blockIdx.y * gridDim.x + blockIdx.x] = red[0];
}

// ---------------- pass A: per-point clustering stats ----------------
// one thread per point; 128 threads/block, 232 blocks
__global__ __launch_bounds__(128) void passA(
    const float* __restrict__ z, const float* __restrict__ t1,
    const float* __restrict__ clus, float* __restrict__ q,
    int* __restrict__ pred, float* __restrict__ scon,
    float* __restrict__ out, int out_size)
{
    __shared__ float cs[K_C * NZ_C];
    const int tid = threadIdx.x;
    for (int i = tid; i < K_C * NZ_C; i += 128) cs[i] = clus[i];
    __syncthreads();

    const int n = blockIdx.x * 128 + tid;
    // grid is exact, but keep guard
    if (n >= N_PTS) return;

    // cos_mult
    const float tx = t1[n * 3 + 0] * 0.01f;
    const float ty = t1[n * 3 + 1] * 0.01f;
    const float tz = t1[n * 3 + 2] * 0.01f;
    const float cm = tx * ty * tz * 0.99f + 1.0f;

    float zp[NZ_C];
    const float* zr = &z[(size_t)n * NZ_C];
    float mean = 0.f;
#pragma unroll
    for (int i = 0; i < NZ_C; i++) { zp[i] = zr[i] * cm; mean += zp[i]; }
    mean *= (1.0f / NZ_C);
    float var = 0.f;
#pragma unroll
    for (int i = 0; i < NZ_C; i++) { float d = zp[i] - mean; var += d * d; }
    var *= (1.0f / (NZ_C - 1));
    const float invstd = 1.0f / sqrtf(var);
#pragma unroll
    for (int i = 0; i < NZ_C; i++) zp[i] = (zp[i] - mean) * invstd;

    float qsum = 0.f;
    float best = -1.f;
    int bestk = 0;
    float* qrow = &q[(size_t)n * K_C];
    for (int k = 0; k < K_C; k++) {
        const float* c = &cs[k * NZ_C];
        float d = 0.f;
#pragma unroll
        for (int i = 0; i < NZ_C; i++) { float df = zp[i] - c[i]; d = fmaf(df, df, d); }
        float qr = EPS_C + d;   // (1/(eps+dist))^{-1} == eps+dist
        qrow[k] = qr;
        qsum += qr;
        if (qr > best) { best = qr; bestk = k; }
    }
    const float inv = 1.0f / qsum;
    float s = 0.f;
    for (int k = 0; k < K_C; k++) {
        float qn = qrow[k] * inv;
        qrow[k] = qn;
        float l = logf(qn);                       // < 0
        float t = 1.0f - qn;
        float neg_temp = t * t * (-l) * (float)N_PTS;
        s += 1.0f / sqrtf(neg_temp);
    }
    pred[n] = bestk;
    scon[n] = s;
    if (n < out_size) out[n] = (float)bestk;
    atomicAdd(&g_cnt[bestk], 1);
}

// ---------------- u[k] = sum_n q[n][k]  (deterministic column reduce) ----------------
__global__ void ureduce(const float* __restrict__ q) {
    __shared__ float sh[256];
    const int k = blockIdx.x;
    float s = 0.f;
    for (int n = threadIdx.x; n < N_PTS; n += 256) s += q[(size_t)n * K_C + k];
    sh[threadIdx.x] = s;
    __syncthreads();
    for (int o = 128; o > 0; o >>= 1) {
        if (threadIdx.x < o) sh[threadIdx.x] += sh[threadIdx.x + o];
        __syncthreads();
    }
    if (threadIdx.x == 0) g_u[k] = sh[0];
}

// ---------------- S = sum_n scon[n] ----------------
__global__ void sreduce(const float* __restrict__ scon) {
    __shared__ float sh[256];
    float s = 0.f;
    for (int n = threadIdx.x; n < N_PTS; n += 256) s += scon[n];
    sh[threadIdx.x] = s;
    __syncthreads();
    for (int o = 128; o > 0; o >>= 1) {
        if (threadIdx.x < o) sh[threadIdx.x] += sh[threadIdx.x + o];
        __syncthreads();
    }
    if (threadIdx.x == 0) g_S = sh[0];
}

// ---------------- pass B: f[k], u_loss (single block) ----------------
__global__ void passB(const float* __restrict__ clus) {
    __shared__ float sh[256];
    const int tid = threadIdx.x;
    // pairwise cluster distances
    float s = 0.f;
    for (int p = tid; p < K_C * K_C; p += 256) {
        int i = p / K_C, j = p - i * K_C;
        const float* a = &clus[i * NZ_C];
        const float* b = &clus[j * NZ_C];
        float d = 0.f;
#pragma unroll
        for (int t = 0; t < NZ_C; t++) { float df = a[t] - b[t]; d = fmaf(df, df, d); }
        s += d;
    }
    sh[tid] = s;
    __syncthreads();
    for (int o = 128; o > 0; o >>= 1) {
        if (tid < o) sh[tid] += sh[tid + o];
        __syncthreads();
    }
    if (tid == 0) {
        float md = sh[0] / (float)(K_C * K_C - K_C);
        g_uloss = 0.01f / md;

        // standardize u
        float un[K_C], vn[K_C];
        float um = 0.f;
        for (int k = 0; k < K_C; k++) um += g_u[k];
        um /= (float)K_C;
        float uv = 0.f;
        for (int k = 0; k < K_C; k++) { float d = g_u[k] - um; uv += d * d; }
        uv /= (float)(K_C - 1);
        float uis = 1.0f / sqrtf(uv);
        for (int k = 0; k < K_C; k++) un[k] = (g_u[k] - um) * uis;

        // v_vec = sqrt(Ncnt) * S, standardized
        float S = g_S;
        float vm = 0.f;
        for (int k = 0; k < K_C; k++) {
            float nc = (g_cnt[k] > 0) ? (float)g_cnt[k] : 1.0f;
            vn[k] = sqrtf(nc) * S;
            vm += vn[k];
        }
        vm /= (float)K_C;
        float vv = 0.f;
        for (int k = 0; k < K_C; k++) { float d = vn[k] - vm; vv += d * d; }
        vv /= (float)(K_C - 1);
        float vis = 1.0f / sqrtf(vv);
        for (int k = 0; k < K_C; k++) vn[k] = (vn[k] - vm) * vis;

        float umin = un[0], vmin = vn[0];
        for (int k = 1; k < K_C; k++) {
            umin = fminf(umin, un[k]);
            vmin = fminf(vmin, vn[k]);
        }
        for (int k = 0; k < K_C; k++) {
            g_f[k] = (un[k] - umin + 0.001f) + (vn[k] - vmin + 0.001f) + 1.0f;
        }
    }
}

// ---------------- pass C: KL partials ----------------
__global__ __launch_bounds__(128) void passC(const float* __restrict__ q,
                                             float* __restrict__ klp) {
    __shared__ float fsh[K_C];
    __shared__ float sh[128];
    const int tid = threadIdx.x;
    for (int i = tid; i < K_C; i += 128) fsh[i] = g_f[i];
    __syncthreads();
    const int n = blockIdx.x * 128 + tid;
    float kl = 0.f;
    const float* qr = &q[(size_t)n * K_C];
    float ws = 0.f;
    for (int k = 0; k < K_C; k++) {
        float qv = qr[k];
        ws += qv * qv / fsh[k];
    }
    float inv = 1.0f / ws;
    for (int k = 0; k < K_C; k++) {
        float qv = qr[k];
        float p = qv * qv / fsh[k] * inv;
        kl += p * (logf(p) - logf(qv));
    }
    sh[tid] = kl;
    __syncthreads();
    for (int o = 64; o > 0; o >>= 1) {
        if (tid < o) sh[tid] += sh[tid + o];
        __syncthreads();
    }
    if (tid == 0) klp[blockIdx.x] = sh[0];
}

// ---------------- final: loss scalar ----------------
__global__ void finalk(float* __restrict__ out, int out_size) {
    __shared__ float sh[256];
    __shared__ float tot[2];
    const int tid = threadIdx.x;
    float s = 0.f;
    for (int i = tid; i < MSE_PARTIALS; i += 256) s += g_msep[i];
    sh[tid] = s;
    __syncthreads();
    for (int o = 128; o > 0; o >>= 1) {
        if (tid < o) sh[tid] += sh[tid + o];
        __syncthreads();
    }
    if (tid == 0) tot[0] = sh[0];
    __syncthreads();
    s = 0.f;
    for (int i = tid; i < MBLK; i += 256) s += g_klp[i];
    sh[tid] = s;
    __syncthreads();
    for (int o = 128; o > 0; o >>= 1) {
        if (tid < o) sh[tid] += sh[tid + o];
        __syncthreads();
    }
    if (tid == 0) tot[1] = sh[0];
    __syncthreads();
    if (tid == 0) {
        float re_loss = tot[0] / ((float)N_PTS * (float)N_IN_C);
        float kl_loss = tot[1] / ((float)N_PTS * (float)K_C) * 0.01f;
        float loss = kl_loss + re_loss + g_uloss;
        if (out_size > N_PTS) out[N_PTS] = loss;
    }
}

// ---------------- launch ----------------
extern "C" void kernel_launch(void* const* d_in, const int* in_sizes, int n_in,
                              void* d_out, int out_size) {
    const float* x    = (const float*)d_in[0];
    const float* t1   = (const float*)d_in[1];
    const float* clus = (const float*)d_in[2];
    const float* We1  = (const float*)d_in[3];
    const float* be1  = (const float*)d_in[4];
    const float* We2  = (const float*)d_in[5];
    const float* be2  = (const float*)d_in[6];
    const float* We3  = (const float*)d_in[7];
    const float* be3  = (const float*)d_in[8];
    const float* Wz   = (const float*)d_in[9];
    const float* bz   = (const float*)d_in[10];
    const float* Wd1  = (const float*)d_in[11];
    const float* bd1  = (const float*)d_in[12];
    const float* Wd2  = (const float*)d_in[13];
    const float* bd2  = (const float*)d_in[14];
    const float* Wd3  = (const float*)d_in[15];
    const float* bd3  = (const float*)d_in[16];
    const float* Wxb  = (const float*)d_in[17];
    const float* bxb  = (const float*)d_in[18];
    float* out = (float*)d_out;

    float *bufA, *bufB, *zbuf, *qbuf, *scon, *msep, *klp;
    int *pred;
    cudaGetSymbolAddress((void**)&bufA, g_bufA);
    cudaGetSymbolAddress((void**)&bufB, g_bufB);
    cudaGetSymbolAddress((void**)&zbuf, g_zbuf);
    cudaGetSymbolAddress((void**)&qbuf, g_q);
    cudaGetSymbolAddress((void**)&pred, g_pred);
    cudaGetSymbolAddress((void**)&scon, g_Scon);
    cudaGetSymbolAddress((void**)&msep, g_msep);
    cudaGetSymbolAddress((void**)&klp,  g_klp);

    init_kernel<<<1, 128>>>();

    // encoder
    gemm_relu<<<dim3(E1_C / BN, MBLK), 256>>>(x,    We1, be1, bufA, N_PTS, N_IN_C, E1_C, 1);
    gemm_relu<<<dim3(E2_C / BN, MBLK), 256>>>(bufA, We2, be2, bufB, N_PTS, E1_C,  E2_C, 1);
    gemm_relu<<<dim3(E3_C / BN, MBLK), 256>>>(bufB, We3, be3, bufA, N_PTS, E2_C,  E3_C, 1);
    gemm_relu<<<dim3(1,        MBLK), 256>>>(bufA, Wz,  bz,  zbuf, N_PTS, E3_C,  NZ_C, 0);
    // decoder
    gemm_relu<<<dim3(D1_C / BN, MBLK), 256>>>(zbuf, Wd1, bd1, bufB, N_PTS, NZ_C, D1_C, 1);
    gemm_relu<<<dim3(D2_C / BN, MBLK), 256>>>(bufB, Wd2, bd2, bufA, N_PTS, D1_C, D2_C, 1);
    gemm_relu<<<dim3(D3_C / BN, MBLK), 256>>>(bufA, Wd3, bd3, bufB, N_PTS, D2_C, D3_C, 1);
    gemm_mse <<<dim3(N_IN_C / BN, MBLK), 256>>>(bufB, Wxb, bxb, x, msep, N_PTS, D3_C, N_IN_C);

    // clustering
    passA<<<MBLK, 128>>>(zbuf, t1, clus, qbuf, pred, scon, out, out_size);
    ureduce<<<K_C, 256>>>(qbuf);
    sreduce<<<1, 256>>>(scon);
    passB<<<1, 256>>>(clus);
    passC<<<MBLK, 128>>>(qbuf, klp);
    finalk<<<1, 256>>>(out, out_size);
}

// round 2
// speedup vs baseline: 1.2286x; 1.2286x over previous
#include <cuda_runtime.h>
#include <math.h>
#include <stdint.h>
#include <string.h>

// ---------------- problem constants ----------------
#define N_PTS   29696
#define N_IN_C  1024
#define E1_C    512
#define E2_C    512
#define E3_C    2048
#define NZ_C    32
#define D1_C    2048
#define D2_C    512
#define D3_C    512
#define K_C     100
#define EPS_C   1e-5f

// big GEMM tiling (FFMA2 path): 128x128 tile, 16 k-step, 256 threads, 8x8 microtile
#define TM 128
#define TN 128
#define TK 16
#define MBLK (N_PTS / TM)                       // 232
#define MSE_PARTIALS (MBLK * (N_IN_C / TN))     // 232*8 = 1856

// small GEMM (N=32 layer) tiling
#define BM 128
#define BN 64
#define BK 16

// ---------------- scratch (static device globals; no allocation) ----------------
__device__ float g_bufA[(size_t)N_PTS * 2048];
__device__ float g_bufB[(size_t)N_PTS * 2048];
__device__ float g_zbuf[(size_t)N_PTS * NZ_C];
__device__ float g_q[(size_t)N_PTS * K_C];
__device__ int   g_pred[N_PTS];
__device__ float g_Scon[N_PTS];
__device__ float g_u[K_C];
__device__ float g_f[K_C];
__device__ int   g_cnt[K_C];
__device__ float g_S;
__device__ float g_uloss;
__device__ float g_msep[MSE_PARTIALS];
__device__ float g_klp[MBLK];

// ---------------- init ----------------
__global__ void init_kernel() {
    int t = threadIdx.x;
    if (t < K_C) g_cnt[t] = 0;
}

// ---------------- packed fp32 helpers ----------------
__device__ __forceinline__ void ffma2(unsigned long long& acc,
                                      unsigned long long a,
                                      unsigned long long b) {
    asm("fma.rn.f32x2 %0, %1, %2, %0;" : "+l"(acc) : "l"(a), "l"(b));
}
__device__ __forceinline__ unsigned long long bcast2(float a) {
    unsigned long long r;
    asm("mov.b64 %0, {%1, %1};" : "=l"(r) : "f"(a));
    return r;
}

// ---------------- FFMA2 GEMM: C = [relu](A[MxK] @ W[KxN] + bias) ----------------
// requires M%128==0, K%16==0, N%128==0
__global__ __launch_bounds__(256, 2) void gemm128(
    const float* __restrict__ A, const float* __restrict__ W,
    const float* __restrict__ bias, float* __restrict__ C,
    int M, int K, int N, int doRelu)
{
    __shared__ float As[TK][TM + 2];   // padded: conflict-free transposed stores
    __shared__ float Ws[TK][TN];
    const int tid = threadIdx.x;
    const int rowBlock = blockIdx.y * TM;
    const int colBlock = blockIdx.x * TN;
    const int tx = tid & 15;           // 0..15 -> column groups
    const int ty = tid >> 4;           // 0..15 -> row group
    const int rBase = ty * 8;
    // this thread's columns: colBlock + g*32 + tx*2 + {0,1}, g=0..3

    unsigned long long acc[8][4];
#pragma unroll
    for (int i = 0; i < 8; i++)
#pragma unroll
        for (int g = 0; g < 4; g++) acc[i][g] = 0ull;

    // A-load mapping: 2048 floats / 256 thr = 2 float4 each
    const int aRow = tid >> 1;            // 0..127
    const int aK4  = (tid & 1) * 8;       // 0 or 8
    // W-load mapping: 2048 floats / 256 thr = 2 float4 each
    const int wK   = tid >> 4;            // 0..15
    const int wC   = (tid & 15) * 4;      // 0..60 (second load at +64)

    for (int k0 = 0; k0 < K; k0 += TK) {
        // A tile -> transposed smem
#pragma unroll
        for (int h = 0; h < 2; h++) {
            float4 v = *reinterpret_cast<const float4*>(
                &A[(size_t)(rowBlock + aRow) * K + k0 + aK4 + h * 4]);
            As[aK4 + h * 4 + 0][aRow] = v.x;
            As[aK4 + h * 4 + 1][aRow] = v.y;
            As[aK4 + h * 4 + 2][aRow] = v.z;
            As[aK4 + h * 4 + 3][aRow] = v.w;
        }
        // W tile
#pragma unroll
        for (int h = 0; h < 2; h++) {
            float4 v = *reinterpret_cast<const float4*>(
                &W[(size_t)(k0 + wK) * N + colBlock + wC + h * 64]);
            *reinterpret_cast<float4*>(&Ws[wK][wC + h * 64]) = v;
        }
        __syncthreads();
#pragma unroll
        for (int kk = 0; kk < TK; kk++) {
            unsigned long long b2[4];
#pragma unroll
            for (int g = 0; g < 4; g++)
                b2[g] = *reinterpret_cast<const unsigned long long*>(
                    &Ws[kk][g * 32 + tx * 2]);
#pragma unroll
            for (int i = 0; i < 8; i++) {
                unsigned long long aa = bcast2(As[kk][rBase + i]);
#pragma unroll
                for (int g = 0; g < 4; g++) ffma2(acc[i][g], aa, b2[g]);
            }
        }
        __syncthreads();
    }
    // epilogue
    float2 bs[4];
#pragma unroll
    for (int g = 0; g < 4; g++)
        bs[g] = *reinterpret_cast<const float2*>(&bias[colBlock + g * 32 + tx * 2]);
#pragma unroll
    for (int i = 0; i < 8; i++) {
        float* crow = &C[(size_t)(rowBlock + rBase + i) * N + colBlock];
#pragma unroll
        for (int g = 0; g < 4; g++) {
            float2 v;
            memcpy(&v, &acc[i][g], 8);
            v.x += bs[g].x; v.y += bs[g].y;
            if (doRelu) { v.x = fmaxf(v.x, 0.f); v.y = fmaxf(v.y, 0.f); }
            *reinterpret_cast<float2*>(&crow[g * 32 + tx * 2]) = v;
        }
    }
}

// ---------------- FFMA2 GEMM fused with MSE vs x (no x_bar store) ----------------
__global__ __launch_bounds__(256, 2) void gemm_mse128(
    const float* __restrict__ A, const float* __restrict__ W,
    const float* __restrict__ bias, const float* __restrict__ Xref,
    float* __restrict__ partial, int M, int K, int N)
{
    __shared__ float As[TK][TM + 2];
    __shared__ float Ws[TK][TN];
    __shared__ float red[256];
    const int tid = threadIdx.x;
    const int rowBlock = blockIdx.y * TM;
    const int colBlock = blockIdx.x * TN;
    const int tx = tid & 15;
    const int ty = tid >> 4;
    const int rBase = ty * 8;

    unsigned long long acc[8][4];
#pragma unroll
    for (int i = 0; i < 8; i++)
#pragma unroll
        for (int g = 0; g < 4; g++) acc[i][g] = 0ull;

    const int aRow = tid >> 1;
    const int aK4  = (tid & 1) * 8;
    const int wK   = tid >> 4;
    const int wC   = (tid & 15) * 4;

    for (int k0 = 0; k0 < K; k0 += TK) {
#pragma unroll
        for (int h = 0; h < 2; h++) {
            float4 v = *reinterpret_cast<const float4*>(
                &A[(size_t)(rowBlock + aRow) * K + k0 + aK4 + h * 4]);
            As[aK4 + h * 4 + 0][aRow] = v.x;
            As[aK4 + h * 4 + 1][aRow] = v.y;
            As[aK4 + h * 4 + 2][aRow] = v.z;
            As[aK4 + h * 4 + 3][aRow] = v.w;
        }
#pragma unroll
        for (int h = 0; h < 2; h++) {
            float4 v = *reinterpret_cast<const float4*>(
                &W[(size_t)(k0 + wK) * N + colBlock + wC + h * 64]);
            *reinterpret_cast<float4*>(&Ws[wK][wC + h * 64]) = v;
        }
        __syncthreads();
#pragma unroll
        for (int kk = 0; kk < TK; kk++) {
            unsigned long long b2[4];
#pragma unroll
            for (int g = 0; g < 4; g++)
                b2[g] = *reinterpret_cast<const unsigned long long*>(
                    &Ws[kk][g * 32 + tx * 2]);
#pragma unroll
            for (int i = 0; i < 8; i++) {
                unsigned long long aa = bcast2(As[kk][rBase + i]);
#pragma unroll
                for (int g = 0; g < 4; g++) ffma2(acc[i][g], aa, b2[g]);
            }
        }
        __syncthreads();
    }
    float2 bs[4];
#pragma unroll
    for (int g = 0; g < 4; g++)
        bs[g] = *reinterpret_cast<const float2*>(&bias[colBlock + g * 32 + tx * 2]);
    float mse = 0.f;
#pragma unroll
    for (int i = 0; i < 8; i++) {
        const float* xrow = &Xref[(size_t)(rowBlock + rBase + i) * N + colBlock];
#pragma unroll
        for (int g = 0; g < 4; g++) {
            float2 v;
            memcpy(&v, &acc[i][g], 8);
            float2 xr = *reinterpret_cast<const float2*>(&xrow[g * 32 + tx * 2]);
            float dx = v.x + bs[g].x - xr.x;
            float dy = v.y + bs[g].y - xr.y;
            mse = fmaf(dx, dx, mse);
            mse = fmaf(dy, dy, mse);
        }
    }
    red[tid] = mse;
    __syncthreads();
    for (int o = 128; o > 0; o >>= 1) {
        if (tid < o) red[tid] += red[tid + o];
        __syncthreads();
    }
    if (tid == 0) partial[blockIdx.y * gridDim.x + blockIdx.x] = red[0];
}

// ---------------- small-N fp32 GEMM (used for the N=32 z layer) ----------------
__global__ __launch_bounds__(256) void gemm_relu(
    const float* __restrict__ A, const float* __restrict__ W,
    const float* __restrict__ bias, float* __restrict__ C,
    int M, int K, int N, int doRelu)
{
    __shared__ float As[BK][BM];
    __shared__ float Ws[BK][BN];
    const int tid = threadIdx.x;
    const int rowBlock = blockIdx.y * BM;
    const int colBlock = blockIdx.x * BN;
    const int tx = tid & 15;
    const int ty = tid >> 4;
    const int rBase = ty * 8;
    const int cBase = tx * 4;

    float acc[8][4];
#pragma unroll
    for (int i = 0; i < 8; i++)
#pragma unroll
        for (int j = 0; j < 4; j++) acc[i][j] = 0.f;

    const int aRow0 = tid >> 2;
    const int aF4   = tid & 3;
    const int wK    = tid >> 4;
    const int wC    = (tid & 15) * 4;

    for (int k0 = 0; k0 < K; k0 += BK) {
#pragma unroll
        for (int h = 0; h < 2; h++) {
            int r = aRow0 + h * 64;
            float4 v = *reinterpret_cast<const float4*>(
                &A[(size_t)(rowBlock + r) * K + k0 + aF4 * 4]);
            As[aF4 * 4 + 0][r] = v.x;
            As[aF4 * 4 + 1][r] = v.y;
            As[aF4 * 4 + 2][r] = v.z;
            As[aF4 * 4 + 3][r] = v.w;
        }
        {
            int col = colBlock + wC;
            float4 v = make_float4(0.f, 0.f, 0.f, 0.f);
            if (col + 3 < N) {
                v = *reinterpret_cast<const float4*>(&W[(size_t)(k0 + wK) * N + col]);
            } else {
                float tmp[4] = {0.f, 0.f, 0.f, 0.f};
                for (int j = 0; j < 4; j++)
                    if (col + j < N) tmp[j] = W[(size_t)(k0 + wK) * N + col + j];
                v = make_float4(tmp[0], tmp[1], tmp[2], tmp[3]);
            }
            *reinterpret_cast<float4*>(&Ws[wK][wC]) = v;
        }
        __syncthreads();
#pragma unroll
        for (int kk = 0; kk < BK; kk++) {
            float a[8], b[4];
#pragma unroll
            for (int i = 0; i < 8; i++) a[i] = As[kk][rBase + i];
#pragma unroll
            for (int j = 0; j < 4; j++) b[j] = Ws[kk][cBase + j];
#pragma unroll
            for (int i = 0; i < 8; i++)
#pragma unroll
                for (int j = 0; j < 4; j++) acc[i][j] = fmaf(a[i], b[j], acc[i][j]);
        }
        __syncthreads();
    }
#pragma unroll
    for (int i = 0; i < 8; i++) {
        int row = rowBlock + rBase + i;
#pragma unroll
        for (int j = 0; j < 4; j++) {
            int col = colBlock + cBase + j;
            if (col < N) {
                float v = acc[i][j] + bias[col];
                if (doRelu) v = fmaxf(v, 0.f);
                C[(size_t)row * N + col] = v;
            }
        }
    }
}

// ---------------- pass A: per-point clustering stats ----------------
__global__ __launch_bounds__(128) void passA(
    const float* __restrict__ z, const float* __restrict__ t1,
    const float* __restrict__ clus, float* __restrict__ q,
    int* __restrict__ pred, float* __restrict__ scon,
    float* __restrict__ out, int out_size)
{
    __shared__ float cs[K_C * NZ_C];
    const int tid = threadIdx.x;
    for (int i = tid; i < K_C * NZ_C; i += 128) cs[i] = clus[i];
    __syncthreads();

    const int n = blockIdx.x * 128 + tid;
    if (n >= N_PTS) return;

    const float tx = t1[n * 3 + 0] * 0.01f;
    const float ty = t1[n * 3 + 1] * 0.01f;
    const float tz = t1[n * 3 + 2] * 0.01f;
    const float cm = tx * ty * tz * 0.99f + 1.0f;

    float zp[NZ_C];
    const float* zr = &z[(size_t)n * NZ_C];
    float mean = 0.f;
#pragma unroll
    for (int i = 0; i < NZ_C; i++) { zp[i] = zr[i] * cm; mean += zp[i]; }
    mean *= (1.0f / NZ_C);
    float var = 0.f;
#pragma unroll
    for (int i = 0; i < NZ_C; i++) { float d = zp[i] - mean; var += d * d; }
    var *= (1.0f / (NZ_C - 1));
    const float invstd = 1.0f / sqrtf(var);
#pragma unroll
    for (int i = 0; i < NZ_C; i++) zp[i] = (zp[i] - mean) * invstd;

    float qsum = 0.f;
    float best = -1.f;
    int bestk = 0;
    float* qrow = &q[(size_t)n * K_C];
    for (int k = 0; k < K_C; k++) {
        const float* c = &cs[k * NZ_C];
        float d = 0.f;
#pragma unroll
        for (int i = 0; i < NZ_C; i++) { float df = zp[i] - c[i]; d = fmaf(df, df, d); }
        float qr = EPS_C + d;
        qrow[k] = qr;
        qsum += qr;
        if (qr > best) { best = qr; bestk = k; }
    }
    const float inv = 1.0f / qsum;
    float s = 0.f;
    for (int k = 0; k < K_C; k++) {
        float qn = qrow[k] * inv;
        qrow[k] = qn;
        float l = logf(qn);
        float t = 1.0f - qn;
        float neg_temp = t * t * (-l) * (float)N_PTS;
        s += 1.0f / sqrtf(neg_temp);
    }
    pred[n] = bestk;
    scon[n] = s;
    if (n < out_size) out[n] = (float)bestk;
    atomicAdd(&g_cnt[bestk], 1);
}

// ---------------- u[k] = sum_n q[n][k] ----------------
__global__ void ureduce(const float* __restrict__ q) {
    __shared__ float sh[256];
    const int k = blockIdx.x;
    float s = 0.f;
    for (int n = threadIdx.x; n < N_PTS; n += 256) s += q[(size_t)n * K_C + k];
    sh[threadIdx.x] = s;
    __syncthreads();
    for (int o = 128; o > 0; o >>= 1) {
        if (threadIdx.x < o) sh[threadIdx.x] += sh[threadIdx.x + o];
        __syncthreads();
    }
    if (threadIdx.x == 0) g_u[k] = sh[0];
}

// ---------------- S = sum_n scon[n] ----------------
__global__ void sreduce(const float* __restrict__ scon) {
    __shared__ float sh[256];
    float s = 0.f;
    for (int n = threadIdx.x; n < N_PTS; n += 256) s += scon[n];
    sh[threadIdx.x] = s;
    __syncthreads();
    for (int o = 128; o > 0; o >>= 1) {
        if (threadIdx.x < o) sh[threadIdx.x] += sh[threadIdx.x + o];
        __syncthreads();
    }
    if (threadIdx.x == 0) g_S = sh[0];
}

// ---------------- pass B: f[k], u_loss ----------------
__global__ void passB(const float* __restrict__ clus) {
    __shared__ float sh[256];
    const int tid = threadIdx.x;
    float s = 0.f;
    for (int p = tid; p < K_C * K_C; p += 256) {
        int i = p / K_C, j = p - i * K_C;
        const float* a = &clus[i * NZ_C];
        const float* b = &clus[j * NZ_C];
        float d = 0.f;
#pragma unroll
        for (int t = 0; t < NZ_C; t++) { float df = a[t] - b[t]; d = fmaf(df, df, d); }
        s += d;
    }
    sh[tid] = s;
    __syncthreads();
    for (int o = 128; o > 0; o >>= 1) {
        if (tid < o) sh[tid] += sh[tid + o];
        __syncthreads();
    }
    if (tid == 0) {
        float md = sh[0] / (float)(K_C * K_C - K_C);
        g_uloss = 0.01f / md;

        float un[K_C], vn[K_C];
        float um = 0.f;
        for (int k = 0; k < K_C; k++) um += g_u[k];
        um /= (float)K_C;
        float uv = 0.f;
        for (int k = 0; k < K_C; k++) { float d = g_u[k] - um; uv += d * d; }
        uv /= (float)(K_C - 1);
        float uis = 1.0f / sqrtf(uv);
        for (int k = 0; k < K_C; k++) un[k] = (g_u[k] - um) * uis;

        float S = g_S;
        float vm = 0.f;
        for (int k = 0; k < K_C; k++) {
            float nc = (g_cnt[k] > 0) ? (float)g_cnt[k] : 1.0f;
            vn[k] = sqrtf(nc) * S;
            vm += vn[k];
        }
        vm /= (float)K_C;
        float vv = 0.f;
        for (int k = 0; k < K_C; k++) { float d = vn[k] - vm; vv += d * d; }
        vv /= (float)(K_C - 1);
        float vis = 1.0f / sqrtf(vv);
        for (int k = 0; k < K_C; k++) vn[k] = (vn[k] - vm) * vis;

        float umin = un[0], vmin = vn[0];
        for (int k = 1; k < K_C; k++) {
            umin = fminf(umin, un[k]);
            vmin = fminf(vmin, vn[k]);
        }
        for (int k = 0; k < K_C; k++) {
            g_f[k] = (un[k] - umin + 0.001f) + (vn[k] - vmin + 0.001f) + 1.0f;
        }
    }
}

// ---------------- pass C: KL partials ----------------
__global__ __launch_bounds__(128) void passC(const float* __restrict__ q,
                                             float* __restrict__ klp) {
    __shared__ float fsh[K_C];
    __shared__ float sh[128];
    const int tid = threadIdx.x;
    for (int i = tid; i < K_C; i += 128) fsh[i] = g_f[i];
    __syncthreads();
    const int n = blockIdx.x * 128 + tid;
    float kl = 0.f;
    const float* qr = &q[(size_t)n * K_C];
    float ws = 0.f;
    for (int k = 0; k < K_C; k++) {
        float qv = qr[k];
        ws += qv * qv / fsh[k];
    }
    float inv = 1.0f / ws;
    for (int k = 0; k < K_C; k++) {
        float qv = qr[k];
        float p = qv * qv / fsh[k] * inv;
        kl += p * (logf(p) - logf(qv));
    }
    sh[tid] = kl;
    __syncthreads();
    for (int o = 64; o > 0; o >>= 1) {
        if (tid < o) sh[tid] += sh[tid + o];
        __syncthreads();
    }
    if (tid == 0) klp[blockIdx.x] = sh[0];
}

// ---------------- final: loss scalar ----------------
__global__ void finalk(float* __restrict__ out, int out_size) {
    __shared__ float sh[256];
    __shared__ float tot[2];
    const int tid = threadIdx.x;
    float s = 0.f;
    for (int i = tid; i < MSE_PARTIALS; i += 256) s += g_msep[i];
    sh[tid] = s;
    __syncthreads();
    for (int o = 128; o > 0; o >>= 1) {
        if (tid < o) sh[tid] += sh[tid + o];
        __syncthreads();
    }
    if (tid == 0) tot[0] = sh[0];
    __syncthreads();
    s = 0.f;
    for (int i = tid; i < MBLK; i += 256) s += g_klp[i];
    sh[tid] = s;
    __syncthreads();
    for (int o = 128; o > 0; o >>= 1) {
        if (tid < o) sh[tid] += sh[tid + o];
        __syncthreads();
    }
    if (tid == 0) tot[1] = sh[0];
    __syncthreads();
    if (tid == 0) {
        float re_loss = tot[0] / ((float)N_PTS * (float)N_IN_C);
        float kl_loss = tot[1] / ((float)N_PTS * (float)K_C) * 0.01f;
        float loss = kl_loss + re_loss + g_uloss;
        if (out_size > N_PTS) out[N_PTS] = loss;
    }
}

// ---------------- launch ----------------
extern "C" void kernel_launch(void* const* d_in, const int* in_sizes, int n_in,
                              void* d_out, int out_size) {
    const float* x    = (const float*)d_in[0];
    const float* t1   = (const float*)d_in[1];
    const float* clus = (const float*)d_in[2];
    const float* We1  = (const float*)d_in[3];
    const float* be1  = (const float*)d_in[4];
    const float* We2  = (const float*)d_in[5];
    const float* be2  = (const float*)d_in[6];
    const float* We3  = (const float*)d_in[7];
    const float* be3  = (const float*)d_in[8];
    const float* Wz   = (const float*)d_in[9];
    const float* bz   = (const float*)d_in[10];
    const float* Wd1  = (const float*)d_in[11];
    const float* bd1  = (const float*)d_in[12];
    const float* Wd2  = (const float*)d_in[13];
    const float* bd2  = (const float*)d_in[14];
    const float* Wd3  = (const float*)d_in[15];
    const float* bd3  = (const float*)d_in[16];
    const float* Wxb  = (const float*)d_in[17];
    const float* bxb  = (const float*)d_in[18];
    float* out = (float*)d_out;

    float *bufA, *bufB, *zbuf, *qbuf, *scon, *msep, *klp;
    int *pred;
    cudaGetSymbolAddress((void**)&bufA, g_bufA);
    cudaGetSymbolAddress((void**)&bufB, g_bufB);
    cudaGetSymbolAddress((void**)&zbuf, g_zbuf);
    cudaGetSymbolAddress((void**)&qbuf, g_q);
    cudaGetSymbolAddress((void**)&pred, g_pred);
    cudaGetSymbolAddress((void**)&scon, g_Scon);
    cudaGetSymbolAddress((void**)&msep, g_msep);
    cudaGetSymbolAddress((void**)&klp,  g_klp);

    init_kernel<<<1, 128>>>();

    // encoder
    gemm128<<<dim3(E1_C / TN, MBLK), 256>>>(x,    We1, be1, bufA, N_PTS, N_IN_C, E1_C, 1);
    gemm128<<<dim3(E2_C / TN, MBLK), 256>>>(bufA, We2, be2, bufB, N_PTS, E1_C,  E2_C, 1);
    gemm128<<<dim3(E3_C / TN, MBLK), 256>>>(bufB, We3, be3, bufA, N_PTS, E2_C,  E3_C, 1);
    gemm_relu<<<dim3(1, N_PTS / BM), 256>>>(bufA, Wz, bz, zbuf, N_PTS, E3_C, NZ_C, 0);
    // decoder
    gemm128<<<dim3(D1_C / TN, MBLK), 256>>>(zbuf, Wd1, bd1, bufB, N_PTS, NZ_C, D1_C, 1);
    gemm128<<<dim3(D2_C / TN, MBLK), 256>>>(bufB, Wd2, bd2, bufA, N_PTS, D1_C, D2_C, 1);
    gemm128<<<dim3(D3_C / TN, MBLK), 256>>>(bufA, Wd3, bd3, bufB, N_PTS, D2_C, D3_C, 1);
    gemm_mse128<<<dim3(N_IN_C / TN, MBLK), 256>>>(bufB, Wxb, bxb, x, msep, N_PTS, D3_C, N_IN_C);

    // clustering
    passA<<<MBLK, 128>>>(zbuf, t1, clus, qbuf, pred, scon, out, out_size);
    ureduce<<<K_C, 256>>>(qbuf);
    sreduce<<<1, 256>>>(scon);
    passB<<<1, 256>>>(clus);
    passC<<<MBLK, 128>>>(qbuf, klp);
    finalk<<<1, 256>>>(out, out_size);
}